// round 3
// baseline (speedup 1.0000x reference)
#include <cuda_runtime.h>

// ShortConv1D: causal depthwise conv1d
// x: [B=4, S=4096, D=2048] f32, w: [D, K=4], b: [D]
// out[b,t,d] = b[d] + sum_k w[d,k] * x[b, t+k-(K-1), d]
//
// HBM-bound kernel: each thread owns 4 contiguous channels (float4 along D)
// and walks T consecutive timesteps with a register sliding window, so x is
// read (T+3)/T times instead of 4 times.

constexpr int BATCH = 4;
constexpr int SEQ   = 4096;
constexpr int DIM   = 2048;
constexpr int D4    = DIM / 4;      // 512 float4 per (b,t) row
constexpr int KTAP  = 4;
constexpr int TSTEP = 32;           // timesteps per thread
constexpr int BLOCK = 256;

__global__ void __launch_bounds__(BLOCK)
shortconv1d_kernel(const float4* __restrict__ x4,
                   const float4* __restrict__ w4,   // [D] float4: 4 taps of channel d
                   const float4* __restrict__ b4,   // [D4]
                   float4* __restrict__ y4)
{
    const int d4 = blockIdx.x * BLOCK + threadIdx.x;   // 0..511 (grid.x = 2)
    const int t0 = blockIdx.y * TSTEP;                 // grid.y = SEQ/TSTEP = 128
    const int bb = blockIdx.z;                         // grid.z = 4

    // Per-channel taps: w is [D, K] row-major, so the 4 taps of channel c are
    // a contiguous float4 at w4[c].
    const int c0 = d4 * 4;
    const float4 wc0 = w4[c0 + 0];
    const float4 wc1 = w4[c0 + 1];
    const float4 wc2 = w4[c0 + 2];
    const float4 wc3 = w4[c0 + 3];
    const float4 bias = b4[d4];

    const float4* xb = x4 + (size_t)bb * SEQ * D4 + d4;
    float4*       yb = y4 + (size_t)bb * SEQ * D4 + d4;

    const float4 zero = make_float4(0.f, 0.f, 0.f, 0.f);

    // Sliding window: h0 = x[t-3], h1 = x[t-2], h2 = x[t-1]
    float4 h0 = (t0 >= 3) ? xb[(size_t)(t0 - 3) * D4] : zero;
    float4 h1 = (t0 >= 2) ? xb[(size_t)(t0 - 2) * D4] : zero;
    float4 h2 = (t0 >= 1) ? xb[(size_t)(t0 - 1) * D4] : zero;

#pragma unroll
    for (int i = 0; i < TSTEP; i++) {
        const float4 cur = xb[(size_t)(t0 + i) * D4];
        float4 o;
        // tap k=0 multiplies x[t-3] ... tap k=3 multiplies x[t]
        o.x = bias.x + wc0.x * h0.x + wc0.y * h1.x + wc0.z * h2.x + wc0.w * cur.x;
        o.y = bias.y + wc1.x * h0.y + wc1.y * h1.y + wc1.z * h2.y + wc1.w * cur.y;
        o.z = bias.z + wc2.x * h0.z + wc2.y * h1.z + wc2.z * h2.z + wc2.w * cur.z;
        o.w = bias.w + wc3.x * h0.w + wc3.y * h1.w + wc3.z * h2.w + wc3.w * cur.w;
        yb[(size_t)(t0 + i) * D4] = o;
        h0 = h1; h1 = h2; h2 = cur;
    }
}

extern "C" void kernel_launch(void* const* d_in, const int* in_sizes, int n_in,
                              void* d_out, int out_size)
{
    const float4* x4 = (const float4*)d_in[0];
    const float4* w4 = (const float4*)d_in[1];
    const float4* b4 = (const float4*)d_in[2];
    float4*       y4 = (float4*)d_out;

    dim3 grid(D4 / BLOCK, SEQ / TSTEP, BATCH);
    shortconv1d_kernel<<<grid, BLOCK>>>(x4, w4, b4, y4);
}